// round 13
// baseline (speedup 1.0000x reference)
#include <cuda_runtime.h>

typedef unsigned long long ull;

#define NB 8
#define NN 2048
#define NITERS 50

// K = log2(e)/eps, eps = 0.005
#define KC 288.53900817779268f
// C1 = eps*log_mu = -0.005*ln(2048)
#define C1F (-0.038123094930796994f)
// C2 = eps*ln(2)
#define C2F 0.0034657359027997265f

// SoA coordinate/norm arrays (x-side and y-side), duals, partials.
__device__ float g_xx[NB*NN], g_xy[NB*NN], g_xz[NB*NN], g_xw[NB*NN];
__device__ float g_yx[NB*NN], g_yy[NB*NN], g_yz[NB*NN], g_yw[NB*NN];
__device__ float g_f[NB*NN], g_g[NB*NN];
__device__ float g_part[512];

__device__ __forceinline__ float ex2f_(float x) {
    float r; asm("ex2.approx.ftz.f32 %0, %1;" : "=f"(r) : "f"(x)); return r;
}
__device__ __forceinline__ float lg2f_(float x) {
    float r; asm("lg2.approx.ftz.f32 %0, %1;" : "=f"(r) : "f"(x)); return r;
}
// packed f32x2 helpers (sm_103a)
__device__ __forceinline__ ull ffma2u(ull a, ull b, ull c) {
    ull d; asm("fma.rn.f32x2 %0, %1, %2, %3;" : "=l"(d) : "l"(a), "l"(b), "l"(c)); return d;
}
__device__ __forceinline__ ull fadd2u(ull a, ull b) {
    ull d; asm("add.rn.f32x2 %0, %1, %2;" : "=l"(d) : "l"(a), "l"(b)); return d;
}
__device__ __forceinline__ ull f2u(float lo, float hi) {
    ull r; asm("mov.b64 %0, {%1, %2};" : "=l"(r) : "f"(lo), "f"(hi)); return r;
}
__device__ __forceinline__ float2 u2f(ull v) {
    float2 f; asm("mov.b64 {%0, %1}, %2;" : "=f"(f.x), "=f"(f.y) : "l"(v)); return f;
}

// Pack coordinates + squared norms into SoA arrays, zero duals.
__global__ void prep_kernel(const float* __restrict__ x, const float* __restrict__ y) {
    int i = blockIdx.x * blockDim.x + threadIdx.x;
    if (i >= NB * NN) return;
    float x0 = x[3*i], x1 = x[3*i+1], x2 = x[3*i+2];
    g_xx[i] = x0; g_xy[i] = x1; g_xz[i] = x2;
    g_xw[i] = x0*x0 + x1*x1 + x2*x2;
    float y0 = y[3*i], y1 = y[3*i+1], y2 = y[3*i+2];
    g_yx[i] = y0; g_yy[i] = y1; g_yz[i] = y2;
    g_yw[i] = y0*y0 + y1*y1 + y2*y2;
    g_f[i] = 0.f; g_g[i] = 0.f;
}

// One chunk of 8 columns: packed f32x2 dot, chunk-max rescale, f32 ex2, sum.
__device__ __forceinline__ void chunk8(const float* __restrict__ syx,
                                       const float* __restrict__ syy,
                                       const float* __restrict__ syz,
                                       const float* __restrict__ sgh,
                                       int m, ull axp, ull ayp, ull azp,
                                       float& mx, float& s) {
    ulonglong2 X0 = *(const ulonglong2*)(syx + m);
    ulonglong2 X1 = *(const ulonglong2*)(syx + m + 4);
    ulonglong2 Y0 = *(const ulonglong2*)(syy + m);
    ulonglong2 Y1 = *(const ulonglong2*)(syy + m + 4);
    ulonglong2 Z0 = *(const ulonglong2*)(syz + m);
    ulonglong2 Z1 = *(const ulonglong2*)(syz + m + 4);
    ulonglong2 G0 = *(const ulonglong2*)(sgh + m);
    ulonglong2 G1 = *(const ulonglong2*)(sgh + m + 4);

    ull p0 = ffma2u(axp, X0.x, ffma2u(ayp, Y0.x, ffma2u(azp, Z0.x, G0.x)));
    ull p1 = ffma2u(axp, X0.y, ffma2u(ayp, Y0.y, ffma2u(azp, Z0.y, G0.y)));
    ull p2 = ffma2u(axp, X1.x, ffma2u(ayp, Y1.x, ffma2u(azp, Z1.x, G1.x)));
    ull p3 = ffma2u(axp, X1.y, ffma2u(ayp, Y1.y, ffma2u(azp, Z1.y, G1.y)));

    float2 f0 = u2f(p0), f1 = u2f(p1), f2v = u2f(p2), f3 = u2f(p3);
    float cm = fmaxf(fmaxf(fmaxf(f0.x, f0.y), fmaxf(f1.x, f1.y)),
                     fmaxf(fmaxf(f2v.x, f2v.y), fmaxf(f3.x, f3.y)));
    float nm = fmaxf(mx, cm);
    float r  = ex2f_(mx - nm);       // ex2(0)=1 exactly when max unchanged
    mx = nm;

    ull nmp = f2u(-nm, -nm);
    float2 q0 = u2f(fadd2u(p0, nmp));
    float2 q1 = u2f(fadd2u(p1, nmp));
    float2 q2 = u2f(fadd2u(p2, nmp));
    float2 q3 = u2f(fadd2u(p3, nmp));

    float e0 = ex2f_(q0.x), e1 = ex2f_(q0.y);
    float e2 = ex2f_(q1.x), e3 = ex2f_(q1.y);
    float e4 = ex2f_(q2.x), e5 = ex2f_(q2.y);
    float e6 = ex2f_(q3.x), e7 = ex2f_(q3.y);
    float sum = ((e0 + e1) + (e2 + e3)) + ((e4 + e5) + (e6 + e7));
    s = fmaf(s, r, sum);
}

// One Sinkhorn half-step. dir==0: f from g (rows = x pts), dir==1: g from f.
// CTA = 512 thr = 16 warps, covers 64 rows x 2048 cols of one batch.
// warp w: row-half h = w>>3 (rows rowbase + h*32 + lane), strip = w&7
// (cols [strip*256, strip*256+256)), 2 independent accumulator streams.
// grid = 256 CTAs at 2 CTAs/SM -> ALL resident, single wave, no tail.
__global__ __launch_bounds__(512, 2) void upd_kernel(int dir) {
    const float *rx, *ry, *rz, *rw, *cx, *cy, *cz, *cw, *din;
    float* dout;
    if (dir == 0) {
        rx = g_xx; ry = g_xy; rz = g_xz; rw = g_xw;
        cx = g_yx; cy = g_yy; cz = g_yz; cw = g_yw;
        din = g_g; dout = g_f;
    } else {
        rx = g_yx; ry = g_yy; rz = g_yz; rw = g_yw;
        cx = g_xx; cy = g_xy; cz = g_xz; cw = g_xw;
        din = g_f; dout = g_g;
    }

    __shared__ __align__(16) float syx[NN], syy[NN], syz[NN], sgh[NN];
    __shared__ float pm[16][32], ps[16][32];

    int tid     = threadIdx.x;
    int c       = blockIdx.x;
    int b       = c >> 5;                 // 32 CTAs per batch
    int base    = b * NN;
    int rowbase = (c & 31) << 6;          // 64 rows per CTA

    // fill SoA smem, gh = K*(din - |y|^2); 512 thr * 4 = 2048 -> one pass
    {
        int i = tid * 4;
        float4 vx = *(const float4*)(cx + base + i);
        float4 vy = *(const float4*)(cy + base + i);
        float4 vz = *(const float4*)(cz + base + i);
        float4 vw = *(const float4*)(cw + base + i);
        float4 vd = *(const float4*)(din + base + i);
        *(float4*)(syx + i) = vx;
        *(float4*)(syy + i) = vy;
        *(float4*)(syz + i) = vz;
        float4 g;
        g.x = KC * (vd.x - vw.x); g.y = KC * (vd.y - vw.y);
        g.z = KC * (vd.z - vw.z); g.w = KC * (vd.w - vw.w);
        *(float4*)(sgh + i) = g;
    }
    __syncthreads();

    int w     = tid >> 5;
    int lane  = tid & 31;
    int h     = w >> 3;                   // row half
    int strip = w & 7;                    // 256-col strip
    int n     = rowbase + (h << 5) + lane;

    float xb = rx[base + n], yb = ry[base + n], zb = rz[base + n], wb = rw[base + n];
    float ax = 2.f * KC * xb, ay = 2.f * KC * yb, az = 2.f * KC * zb;
    ull axp = f2u(ax, ax), ayp = f2u(ay, ay), azp = f2u(az, az);

    float mx0 = -1e30f, s0 = 0.f;
    float mx1 = -1e30f, s1 = 0.f;
    int m0 = strip << 8;                  // 256-col strip

#pragma unroll 1
    for (int m = m0; m < m0 + 256; m += 16) {
        chunk8(syx, syy, syz, sgh, m,     axp, ayp, azp, mx0, s0);
        chunk8(syx, syy, syz, sgh, m + 8, axp, ayp, azp, mx1, s1);
    }

    // merge the two streams
    float M = fmaxf(mx0, mx1);
    float S = fmaf(s0, ex2f_(mx0 - M), s1 * ex2f_(mx1 - M));

    pm[w][lane] = M;
    ps[w][lane] = S;
    __syncthreads();

    // warps 0 and 8 merge the 8 strips of their row half
    if (strip == 0) {
        int j0 = h << 3;
        float Mm = pm[j0][lane];
#pragma unroll
        for (int j = 1; j < 8; j++) Mm = fmaxf(Mm, pm[j0 + j][lane]);
        float Sm = 0.f;
#pragma unroll
        for (int j = 0; j < 8; j++) Sm += ps[j0 + j][lane] * ex2f_(pm[j0 + j][lane] - Mm);
        // reapply the per-row shift -K*|x_n|^2 dropped from the loop
        float lse2 = (Mm - KC * wb) + lg2f_(Sm);
        dout[base + n] = C1F - C2F * lse2;   // eps*log_mu - eps*ln2*lse2
    }
}

// dis sum: total = sum_{b,n,m} exp((f+g-C)/eps) * C;  result = total / B
__global__ __launch_bounds__(256) void fin_kernel() {
    __shared__ __align__(16) float syx[NN], syy[NN], syz[NN], syw[NN], sg[NN];
    __shared__ float wsum[8];

    int tid  = threadIdx.x;
    int b    = blockIdx.x >> 6;
    int base = b * NN;

    for (int i = tid * 4; i < NN; i += 1024) {
        *(float4*)(syx + i) = *(const float4*)(g_yx + base + i);
        *(float4*)(syy + i) = *(const float4*)(g_yy + base + i);
        *(float4*)(syz + i) = *(const float4*)(g_yz + base + i);
        *(float4*)(syw + i) = *(const float4*)(g_yw + base + i);
        *(float4*)(sg  + i) = *(const float4*)(g_g  + base + i);
    }
    __syncthreads();

    int w    = tid >> 5;
    int lane = tid & 31;
    int n    = ((blockIdx.x & 63) << 5) + lane;

    float xb = g_xx[base + n], yb = g_xy[base + n], zb = g_xz[base + n], wb = g_xw[base + n];
    float Kf = KC * g_f[base + n];
    float acc = 0.f;

    int m0 = w << 8;
    for (int m = m0; m < m0 + 256; ++m) {
        float d = fmaf(xb, syx[m], fmaf(yb, syy[m], zb * syz[m]));
        float c = fmaf(-2.f, d, wb + syw[m]);
        c = fmaxf(c, 0.f);
        float arg = fmaf(KC, sg[m] - c, Kf);   // K*(f + g - c)
        acc = fmaf(ex2f_(arg), c, acc);        // underflow -> 0 harmlessly
    }

    for (int o = 16; o; o >>= 1) acc += __shfl_xor_sync(0xffffffffu, acc, o);
    if (lane == 0) wsum[w] = acc;
    __syncthreads();
    if (tid == 0) {
        float t = 0.f;
#pragma unroll
        for (int j = 0; j < 8; j++) t += wsum[j];
        g_part[blockIdx.x] = t;
    }
}

// Deterministic final reduction of 512 block partials.
__global__ void red_kernel(float* __restrict__ out) {
    __shared__ float sm[512];
    int t = threadIdx.x;
    sm[t] = g_part[t];
    __syncthreads();
    for (int o = 256; o; o >>= 1) {
        if (t < o) sm[t] += sm[t + o];
        __syncthreads();
    }
    if (t == 0) out[0] = sm[0] * 0.125f;   // / B
}

extern "C" void kernel_launch(void* const* d_in, const int* in_sizes, int n_in,
                              void* d_out, int out_size) {
    const float* x = (const float*)d_in[0];
    const float* y = (const float*)d_in[1];

    prep_kernel<<<(NB * NN + 255) / 256, 256>>>(x, y);

    for (int it = 0; it < NITERS; ++it) {
        upd_kernel<<<256, 512>>>(0);   // f from g
        upd_kernel<<<256, 512>>>(1);   // g from new f
    }

    fin_kernel<<<512, 256>>>();
    red_kernel<<<1, 512>>>((float*)d_out);
}

// round 14
// speedup vs baseline: 1.0004x; 1.0004x over previous
#include <cuda_runtime.h>

typedef unsigned long long ull;

#define NB 8
#define NN 2048
#define NITERS 50

// K = log2(e)/eps, eps = 0.005
#define KC 288.53900817779268f
// C1 = eps*log_mu = -0.005*ln(2048)
#define C1F (-0.038123094930796994f)
// C2 = eps*ln(2)
#define C2F 0.0034657359027997265f

// SoA coordinate/norm arrays (x-side and y-side), duals, partials.
__device__ float g_xx[NB*NN], g_xy[NB*NN], g_xz[NB*NN], g_xw[NB*NN];
__device__ float g_yx[NB*NN], g_yy[NB*NN], g_yz[NB*NN], g_yw[NB*NN];
__device__ float g_f[NB*NN], g_g[NB*NN];
__device__ float g_part[512];

__device__ __forceinline__ float ex2f_(float x) {
    float r; asm("ex2.approx.ftz.f32 %0, %1;" : "=f"(r) : "f"(x)); return r;
}
__device__ __forceinline__ float lg2f_(float x) {
    float r; asm("lg2.approx.ftz.f32 %0, %1;" : "=f"(r) : "f"(x)); return r;
}
// packed f32x2 helpers (sm_103a)
__device__ __forceinline__ ull ffma2u(ull a, ull b, ull c) {
    ull d; asm("fma.rn.f32x2 %0, %1, %2, %3;" : "=l"(d) : "l"(a), "l"(b), "l"(c)); return d;
}
__device__ __forceinline__ ull fadd2u(ull a, ull b) {
    ull d; asm("add.rn.f32x2 %0, %1, %2;" : "=l"(d) : "l"(a), "l"(b)); return d;
}
__device__ __forceinline__ ull f2u(float lo, float hi) {
    ull r; asm("mov.b64 %0, {%1, %2};" : "=l"(r) : "f"(lo), "f"(hi)); return r;
}
__device__ __forceinline__ float2 u2f(ull v) {
    float2 f; asm("mov.b64 {%0, %1}, %2;" : "=f"(f.x), "=f"(f.y) : "l"(v)); return f;
}

// Pack coordinates + squared norms into SoA arrays, zero duals.
__global__ void prep_kernel(const float* __restrict__ x, const float* __restrict__ y) {
    int i = blockIdx.x * blockDim.x + threadIdx.x;
    if (i >= NB * NN) return;
    float x0 = x[3*i], x1 = x[3*i+1], x2 = x[3*i+2];
    g_xx[i] = x0; g_xy[i] = x1; g_xz[i] = x2;
    g_xw[i] = x0*x0 + x1*x1 + x2*x2;
    float y0 = y[3*i], y1 = y[3*i+1], y2 = y[3*i+2];
    g_yx[i] = y0; g_yy[i] = y1; g_yz[i] = y2;
    g_yw[i] = y0*y0 + y1*y1 + y2*y2;
    g_f[i] = 0.f; g_g[i] = 0.f;
}

// One chunk of 8 columns: packed f32x2 dot, chunk-max rescale, f32 ex2, sum.
__device__ __forceinline__ void chunk8(const float* __restrict__ syx,
                                       const float* __restrict__ syy,
                                       const float* __restrict__ syz,
                                       const float* __restrict__ sgh,
                                       int m, ull axp, ull ayp, ull azp,
                                       float& mx, float& s) {
    ulonglong2 X0 = *(const ulonglong2*)(syx + m);
    ulonglong2 X1 = *(const ulonglong2*)(syx + m + 4);
    ulonglong2 Y0 = *(const ulonglong2*)(syy + m);
    ulonglong2 Y1 = *(const ulonglong2*)(syy + m + 4);
    ulonglong2 Z0 = *(const ulonglong2*)(syz + m);
    ulonglong2 Z1 = *(const ulonglong2*)(syz + m + 4);
    ulonglong2 G0 = *(const ulonglong2*)(sgh + m);
    ulonglong2 G1 = *(const ulonglong2*)(sgh + m + 4);

    ull p0 = ffma2u(axp, X0.x, ffma2u(ayp, Y0.x, ffma2u(azp, Z0.x, G0.x)));
    ull p1 = ffma2u(axp, X0.y, ffma2u(ayp, Y0.y, ffma2u(azp, Z0.y, G0.y)));
    ull p2 = ffma2u(axp, X1.x, ffma2u(ayp, Y1.x, ffma2u(azp, Z1.x, G1.x)));
    ull p3 = ffma2u(axp, X1.y, ffma2u(ayp, Y1.y, ffma2u(azp, Z1.y, G1.y)));

    float2 f0 = u2f(p0), f1 = u2f(p1), f2v = u2f(p2), f3 = u2f(p3);
    float cm = fmaxf(fmaxf(fmaxf(f0.x, f0.y), fmaxf(f1.x, f1.y)),
                     fmaxf(fmaxf(f2v.x, f2v.y), fmaxf(f3.x, f3.y)));
    float nm = fmaxf(mx, cm);
    float r  = ex2f_(mx - nm);       // ex2(0)=1 exactly when max unchanged
    mx = nm;

    ull nmp = f2u(-nm, -nm);
    float2 q0 = u2f(fadd2u(p0, nmp));
    float2 q1 = u2f(fadd2u(p1, nmp));
    float2 q2 = u2f(fadd2u(p2, nmp));
    float2 q3 = u2f(fadd2u(p3, nmp));

    float e0 = ex2f_(q0.x), e1 = ex2f_(q0.y);
    float e2 = ex2f_(q1.x), e3 = ex2f_(q1.y);
    float e4 = ex2f_(q2.x), e5 = ex2f_(q2.y);
    float e6 = ex2f_(q3.x), e7 = ex2f_(q3.y);
    float sum = ((e0 + e1) + (e2 + e3)) + ((e4 + e5) + (e6 + e7));
    s = fmaf(s, r, sum);
}

// One Sinkhorn half-step. dir==0: f from g (rows = x pts), dir==1: g from f.
// CTA = 512 thr = 16 warps, covers 64 rows x 2048 cols of one batch.
// warp w: row-half h = w>>3 (rows rowbase + h*32 + lane), strip = w&7
// (cols [strip*256, strip*256+256)), 2 independent accumulator streams.
// grid = 256 CTAs at 2 CTAs/SM -> ALL resident, single wave, no tail.
__global__ __launch_bounds__(512, 2) void upd_kernel(int dir) {
    const float *rx, *ry, *rz, *rw, *cx, *cy, *cz, *cw, *din;
    float* dout;
    if (dir == 0) {
        rx = g_xx; ry = g_xy; rz = g_xz; rw = g_xw;
        cx = g_yx; cy = g_yy; cz = g_yz; cw = g_yw;
        din = g_g; dout = g_f;
    } else {
        rx = g_yx; ry = g_yy; rz = g_yz; rw = g_yw;
        cx = g_xx; cy = g_xy; cz = g_xz; cw = g_xw;
        din = g_f; dout = g_g;
    }

    __shared__ __align__(16) float syx[NN], syy[NN], syz[NN], sgh[NN];
    __shared__ float pm[16][32], ps[16][32];

    int tid     = threadIdx.x;
    int c       = blockIdx.x;
    int b       = c >> 5;                 // 32 CTAs per batch
    int base    = b * NN;
    int rowbase = (c & 31) << 6;          // 64 rows per CTA

    // fill SoA smem, gh = K*(din - |y|^2); 512 thr * 4 = 2048 -> one pass
    {
        int i = tid * 4;
        float4 vx = *(const float4*)(cx + base + i);
        float4 vy = *(const float4*)(cy + base + i);
        float4 vz = *(const float4*)(cz + base + i);
        float4 vw = *(const float4*)(cw + base + i);
        float4 vd = *(const float4*)(din + base + i);
        *(float4*)(syx + i) = vx;
        *(float4*)(syy + i) = vy;
        *(float4*)(syz + i) = vz;
        float4 g;
        g.x = KC * (vd.x - vw.x); g.y = KC * (vd.y - vw.y);
        g.z = KC * (vd.z - vw.z); g.w = KC * (vd.w - vw.w);
        *(float4*)(sgh + i) = g;
    }
    __syncthreads();

    int w     = tid >> 5;
    int lane  = tid & 31;
    int h     = w >> 3;                   // row half
    int strip = w & 7;                    // 256-col strip
    int n     = rowbase + (h << 5) + lane;

    float xb = rx[base + n], yb = ry[base + n], zb = rz[base + n], wb = rw[base + n];
    float ax = 2.f * KC * xb, ay = 2.f * KC * yb, az = 2.f * KC * zb;
    ull axp = f2u(ax, ax), ayp = f2u(ay, ay), azp = f2u(az, az);

    float mx0 = -1e30f, s0 = 0.f;
    float mx1 = -1e30f, s1 = 0.f;
    int m0 = strip << 8;                  // 256-col strip

#pragma unroll 1
    for (int m = m0; m < m0 + 256; m += 16) {
        chunk8(syx, syy, syz, sgh, m,     axp, ayp, azp, mx0, s0);
        chunk8(syx, syy, syz, sgh, m + 8, axp, ayp, azp, mx1, s1);
    }

    // merge the two streams
    float M = fmaxf(mx0, mx1);
    float S = fmaf(s0, ex2f_(mx0 - M), s1 * ex2f_(mx1 - M));

    pm[w][lane] = M;
    ps[w][lane] = S;
    __syncthreads();

    // warps 0 and 8 merge the 8 strips of their row half
    if (strip == 0) {
        int j0 = h << 3;
        float Mm = pm[j0][lane];
#pragma unroll
        for (int j = 1; j < 8; j++) Mm = fmaxf(Mm, pm[j0 + j][lane]);
        float Sm = 0.f;
#pragma unroll
        for (int j = 0; j < 8; j++) Sm += ps[j0 + j][lane] * ex2f_(pm[j0 + j][lane] - Mm);
        // reapply the per-row shift -K*|x_n|^2 dropped from the loop
        float lse2 = (Mm - KC * wb) + lg2f_(Sm);
        dout[base + n] = C1F - C2F * lse2;   // eps*log_mu - eps*ln2*lse2
    }
}

// dis sum: total = sum_{b,n,m} exp((f+g-C)/eps) * C;  result = total / B
__global__ __launch_bounds__(256) void fin_kernel() {
    __shared__ __align__(16) float syx[NN], syy[NN], syz[NN], syw[NN], sg[NN];
    __shared__ float wsum[8];

    int tid  = threadIdx.x;
    int b    = blockIdx.x >> 6;
    int base = b * NN;

    for (int i = tid * 4; i < NN; i += 1024) {
        *(float4*)(syx + i) = *(const float4*)(g_yx + base + i);
        *(float4*)(syy + i) = *(const float4*)(g_yy + base + i);
        *(float4*)(syz + i) = *(const float4*)(g_yz + base + i);
        *(float4*)(syw + i) = *(const float4*)(g_yw + base + i);
        *(float4*)(sg  + i) = *(const float4*)(g_g  + base + i);
    }
    __syncthreads();

    int w    = tid >> 5;
    int lane = tid & 31;
    int n    = ((blockIdx.x & 63) << 5) + lane;

    float xb = g_xx[base + n], yb = g_xy[base + n], zb = g_xz[base + n], wb = g_xw[base + n];
    float Kf = KC * g_f[base + n];
    float acc = 0.f;

    int m0 = w << 8;
    for (int m = m0; m < m0 + 256; ++m) {
        float d = fmaf(xb, syx[m], fmaf(yb, syy[m], zb * syz[m]));
        float c = fmaf(-2.f, d, wb + syw[m]);
        c = fmaxf(c, 0.f);
        float arg = fmaf(KC, sg[m] - c, Kf);   // K*(f + g - c)
        acc = fmaf(ex2f_(arg), c, acc);        // underflow -> 0 harmlessly
    }

    for (int o = 16; o; o >>= 1) acc += __shfl_xor_sync(0xffffffffu, acc, o);
    if (lane == 0) wsum[w] = acc;
    __syncthreads();
    if (tid == 0) {
        float t = 0.f;
#pragma unroll
        for (int j = 0; j < 8; j++) t += wsum[j];
        g_part[blockIdx.x] = t;
    }
}

// Deterministic final reduction of 512 block partials.
__global__ void red_kernel(float* __restrict__ out) {
    __shared__ float sm[512];
    int t = threadIdx.x;
    sm[t] = g_part[t];
    __syncthreads();
    for (int o = 256; o; o >>= 1) {
        if (t < o) sm[t] += sm[t + o];
        __syncthreads();
    }
    if (t == 0) out[0] = sm[0] * 0.125f;   // / B
}

extern "C" void kernel_launch(void* const* d_in, const int* in_sizes, int n_in,
                              void* d_out, int out_size) {
    const float* x = (const float*)d_in[0];
    const float* y = (const float*)d_in[1];

    prep_kernel<<<(NB * NN + 255) / 256, 256>>>(x, y);

    for (int it = 0; it < NITERS; ++it) {
        upd_kernel<<<256, 512>>>(0);   // f from g
        upd_kernel<<<256, 512>>>(1);   // g from new f
    }

    fin_kernel<<<512, 256>>>();
    red_kernel<<<1, 512>>>((float*)d_out);
}

// round 15
// speedup vs baseline: 1.0016x; 1.0012x over previous
#include <cuda_runtime.h>

typedef unsigned long long ull;

#define NB 8
#define NN 2048
#define NITERS 50

// K = log2(e)/eps, eps = 0.005
#define KC 288.53900817779268f
// C1 = eps*log_mu = -0.005*ln(2048)
#define C1F (-0.038123094930796994f)
// C2 = eps*ln(2)
#define C2F 0.0034657359027997265f

// SoA coordinate/norm arrays (x-side and y-side), duals, partials.
__device__ float g_xx[NB*NN], g_xy[NB*NN], g_xz[NB*NN], g_xw[NB*NN];
__device__ float g_yx[NB*NN], g_yy[NB*NN], g_yz[NB*NN], g_yw[NB*NN];
__device__ float g_f[NB*NN], g_g[NB*NN];
__device__ float g_part[512];

__device__ __forceinline__ float ex2f_(float x) {
    float r; asm("ex2.approx.ftz.f32 %0, %1;" : "=f"(r) : "f"(x)); return r;
}
__device__ __forceinline__ float lg2f_(float x) {
    float r; asm("lg2.approx.ftz.f32 %0, %1;" : "=f"(r) : "f"(x)); return r;
}
// packed f32x2 helpers (sm_103a)
__device__ __forceinline__ ull ffma2u(ull a, ull b, ull c) {
    ull d; asm("fma.rn.f32x2 %0, %1, %2, %3;" : "=l"(d) : "l"(a), "l"(b), "l"(c)); return d;
}
__device__ __forceinline__ ull fadd2u(ull a, ull b) {
    ull d; asm("add.rn.f32x2 %0, %1, %2;" : "=l"(d) : "l"(a), "l"(b)); return d;
}
__device__ __forceinline__ ull f2u(float lo, float hi) {
    ull r; asm("mov.b64 %0, {%1, %2};" : "=l"(r) : "f"(lo), "f"(hi)); return r;
}
__device__ __forceinline__ float2 u2f(ull v) {
    float2 f; asm("mov.b64 {%0, %1}, %2;" : "=f"(f.x), "=f"(f.y) : "l"(v)); return f;
}

// Pack coordinates + squared norms into SoA arrays, zero duals.
__global__ void prep_kernel(const float* __restrict__ x, const float* __restrict__ y) {
    int i = blockIdx.x * blockDim.x + threadIdx.x;
    if (i >= NB * NN) return;
    float x0 = x[3*i], x1 = x[3*i+1], x2 = x[3*i+2];
    g_xx[i] = x0; g_xy[i] = x1; g_xz[i] = x2;
    g_xw[i] = x0*x0 + x1*x1 + x2*x2;
    float y0 = y[3*i], y1 = y[3*i+1], y2 = y[3*i+2];
    g_yx[i] = y0; g_yy[i] = y1; g_yz[i] = y2;
    g_yw[i] = y0*y0 + y1*y1 + y2*y2;
    g_f[i] = 0.f; g_g[i] = 0.f;
}

// One chunk of 8 columns: packed f32x2 dot, chunk-max rescale, f32 ex2, sum.
__device__ __forceinline__ void chunk8(const float* __restrict__ syx,
                                       const float* __restrict__ syy,
                                       const float* __restrict__ syz,
                                       const float* __restrict__ sgh,
                                       int m, ull axp, ull ayp, ull azp,
                                       float& mx, float& s) {
    ulonglong2 X0 = *(const ulonglong2*)(syx + m);
    ulonglong2 X1 = *(const ulonglong2*)(syx + m + 4);
    ulonglong2 Y0 = *(const ulonglong2*)(syy + m);
    ulonglong2 Y1 = *(const ulonglong2*)(syy + m + 4);
    ulonglong2 Z0 = *(const ulonglong2*)(syz + m);
    ulonglong2 Z1 = *(const ulonglong2*)(syz + m + 4);
    ulonglong2 G0 = *(const ulonglong2*)(sgh + m);
    ulonglong2 G1 = *(const ulonglong2*)(sgh + m + 4);

    ull p0 = ffma2u(axp, X0.x, ffma2u(ayp, Y0.x, ffma2u(azp, Z0.x, G0.x)));
    ull p1 = ffma2u(axp, X0.y, ffma2u(ayp, Y0.y, ffma2u(azp, Z0.y, G0.y)));
    ull p2 = ffma2u(axp, X1.x, ffma2u(ayp, Y1.x, ffma2u(azp, Z1.x, G1.x)));
    ull p3 = ffma2u(axp, X1.y, ffma2u(ayp, Y1.y, ffma2u(azp, Z1.y, G1.y)));

    float2 f0 = u2f(p0), f1 = u2f(p1), f2v = u2f(p2), f3 = u2f(p3);
    float cm = fmaxf(fmaxf(fmaxf(f0.x, f0.y), fmaxf(f1.x, f1.y)),
                     fmaxf(fmaxf(f2v.x, f2v.y), fmaxf(f3.x, f3.y)));
    float nm = fmaxf(mx, cm);
    float r  = ex2f_(mx - nm);       // ex2(0)=1 exactly when max unchanged
    mx = nm;

    ull nmp = f2u(-nm, -nm);
    float2 q0 = u2f(fadd2u(p0, nmp));
    float2 q1 = u2f(fadd2u(p1, nmp));
    float2 q2 = u2f(fadd2u(p2, nmp));
    float2 q3 = u2f(fadd2u(p3, nmp));

    float e0 = ex2f_(q0.x), e1 = ex2f_(q0.y);
    float e2 = ex2f_(q1.x), e3 = ex2f_(q1.y);
    float e4 = ex2f_(q2.x), e5 = ex2f_(q2.y);
    float e6 = ex2f_(q3.x), e7 = ex2f_(q3.y);
    float sum = ((e0 + e1) + (e2 + e3)) + ((e4 + e5) + (e6 + e7));
    s = fmaf(s, r, sum);
}

// One Sinkhorn half-step. dir==0: f from g (rows = x pts), dir==1: g from f.
// CTA = 512 thr = 16 warps, covers 64 rows x 2048 cols of one batch.
// warp w: row-half h = w>>3 (rows rowbase + h*32 + lane), strip = w&7
// (cols [strip*256, strip*256+256)), 2 independent accumulator streams.
// grid = 256 CTAs at 2 CTAs/SM -> ALL resident, single wave, no tail.
__global__ __launch_bounds__(512, 2) void upd_kernel(int dir) {
    const float *rx, *ry, *rz, *rw, *cx, *cy, *cz, *cw, *din;
    float* dout;
    if (dir == 0) {
        rx = g_xx; ry = g_xy; rz = g_xz; rw = g_xw;
        cx = g_yx; cy = g_yy; cz = g_yz; cw = g_yw;
        din = g_g; dout = g_f;
    } else {
        rx = g_yx; ry = g_yy; rz = g_yz; rw = g_yw;
        cx = g_xx; cy = g_xy; cz = g_xz; cw = g_xw;
        din = g_f; dout = g_g;
    }

    __shared__ __align__(16) float syx[NN], syy[NN], syz[NN], sgh[NN];
    __shared__ float pm[16][32], ps[16][32];

    int tid     = threadIdx.x;
    int c       = blockIdx.x;
    int b       = c >> 5;                 // 32 CTAs per batch
    int base    = b * NN;
    int rowbase = (c & 31) << 6;          // 64 rows per CTA

    // fill SoA smem, gh = K*(din - |y|^2); 512 thr * 4 = 2048 -> one pass
    {
        int i = tid * 4;
        float4 vx = *(const float4*)(cx + base + i);
        float4 vy = *(const float4*)(cy + base + i);
        float4 vz = *(const float4*)(cz + base + i);
        float4 vw = *(const float4*)(cw + base + i);
        float4 vd = *(const float4*)(din + base + i);
        *(float4*)(syx + i) = vx;
        *(float4*)(syy + i) = vy;
        *(float4*)(syz + i) = vz;
        float4 g;
        g.x = KC * (vd.x - vw.x); g.y = KC * (vd.y - vw.y);
        g.z = KC * (vd.z - vw.z); g.w = KC * (vd.w - vw.w);
        *(float4*)(sgh + i) = g;
    }
    __syncthreads();

    int w     = tid >> 5;
    int lane  = tid & 31;
    int h     = w >> 3;                   // row half
    int strip = w & 7;                    // 256-col strip
    int n     = rowbase + (h << 5) + lane;

    float xb = rx[base + n], yb = ry[base + n], zb = rz[base + n], wb = rw[base + n];
    float ax = 2.f * KC * xb, ay = 2.f * KC * yb, az = 2.f * KC * zb;
    ull axp = f2u(ax, ax), ayp = f2u(ay, ay), azp = f2u(az, az);

    float mx0 = -1e30f, s0 = 0.f;
    float mx1 = -1e30f, s1 = 0.f;
    int m0 = strip << 8;                  // 256-col strip

#pragma unroll 1
    for (int m = m0; m < m0 + 256; m += 16) {
        chunk8(syx, syy, syz, sgh, m,     axp, ayp, azp, mx0, s0);
        chunk8(syx, syy, syz, sgh, m + 8, axp, ayp, azp, mx1, s1);
    }

    // merge the two streams
    float M = fmaxf(mx0, mx1);
    float S = fmaf(s0, ex2f_(mx0 - M), s1 * ex2f_(mx1 - M));

    pm[w][lane] = M;
    ps[w][lane] = S;
    __syncthreads();

    // warps 0 and 8 merge the 8 strips of their row half
    if (strip == 0) {
        int j0 = h << 3;
        float Mm = pm[j0][lane];
#pragma unroll
        for (int j = 1; j < 8; j++) Mm = fmaxf(Mm, pm[j0 + j][lane]);
        float Sm = 0.f;
#pragma unroll
        for (int j = 0; j < 8; j++) Sm += ps[j0 + j][lane] * ex2f_(pm[j0 + j][lane] - Mm);
        // reapply the per-row shift -K*|x_n|^2 dropped from the loop
        float lse2 = (Mm - KC * wb) + lg2f_(Sm);
        dout[base + n] = C1F - C2F * lse2;   // eps*log_mu - eps*ln2*lse2
    }
}

// dis sum: total = sum_{b,n,m} exp((f+g-C)/eps) * C;  result = total / B
__global__ __launch_bounds__(256) void fin_kernel() {
    __shared__ __align__(16) float syx[NN], syy[NN], syz[NN], syw[NN], sg[NN];
    __shared__ float wsum[8];

    int tid  = threadIdx.x;
    int b    = blockIdx.x >> 6;
    int base = b * NN;

    for (int i = tid * 4; i < NN; i += 1024) {
        *(float4*)(syx + i) = *(const float4*)(g_yx + base + i);
        *(float4*)(syy + i) = *(const float4*)(g_yy + base + i);
        *(float4*)(syz + i) = *(const float4*)(g_yz + base + i);
        *(float4*)(syw + i) = *(const float4*)(g_yw + base + i);
        *(float4*)(sg  + i) = *(const float4*)(g_g  + base + i);
    }
    __syncthreads();

    int w    = tid >> 5;
    int lane = tid & 31;
    int n    = ((blockIdx.x & 63) << 5) + lane;

    float xb = g_xx[base + n], yb = g_xy[base + n], zb = g_xz[base + n], wb = g_xw[base + n];
    float Kf = KC * g_f[base + n];
    float acc = 0.f;

    int m0 = w << 8;
    for (int m = m0; m < m0 + 256; ++m) {
        float d = fmaf(xb, syx[m], fmaf(yb, syy[m], zb * syz[m]));
        float c = fmaf(-2.f, d, wb + syw[m]);
        c = fmaxf(c, 0.f);
        float arg = fmaf(KC, sg[m] - c, Kf);   // K*(f + g - c)
        acc = fmaf(ex2f_(arg), c, acc);        // underflow -> 0 harmlessly
    }

    for (int o = 16; o; o >>= 1) acc += __shfl_xor_sync(0xffffffffu, acc, o);
    if (lane == 0) wsum[w] = acc;
    __syncthreads();
    if (tid == 0) {
        float t = 0.f;
#pragma unroll
        for (int j = 0; j < 8; j++) t += wsum[j];
        g_part[blockIdx.x] = t;
    }
}

// Deterministic final reduction of 512 block partials.
__global__ void red_kernel(float* __restrict__ out) {
    __shared__ float sm[512];
    int t = threadIdx.x;
    sm[t] = g_part[t];
    __syncthreads();
    for (int o = 256; o; o >>= 1) {
        if (t < o) sm[t] += sm[t + o];
        __syncthreads();
    }
    if (t == 0) out[0] = sm[0] * 0.125f;   // / B
}

extern "C" void kernel_launch(void* const* d_in, const int* in_sizes, int n_in,
                              void* d_out, int out_size) {
    const float* x = (const float*)d_in[0];
    const float* y = (const float*)d_in[1];

    prep_kernel<<<(NB * NN + 255) / 256, 256>>>(x, y);

    for (int it = 0; it < NITERS; ++it) {
        upd_kernel<<<256, 512>>>(0);   // f from g
        upd_kernel<<<256, 512>>>(1);   // g from new f
    }

    fin_kernel<<<512, 256>>>();
    red_kernel<<<1, 512>>>((float*)d_out);
}

// round 16
// speedup vs baseline: 1.0029x; 1.0013x over previous
#include <cuda_runtime.h>

typedef unsigned long long ull;

#define NB 8
#define NN 2048
#define NITERS 50

// K = log2(e)/eps, eps = 0.005
#define KC 288.53900817779268f
// C1 = eps*log_mu = -0.005*ln(2048)
#define C1F (-0.038123094930796994f)
// C2 = eps*ln(2)
#define C2F 0.0034657359027997265f

// SoA coordinate/norm arrays (x-side and y-side), duals, partials.
__device__ float g_xx[NB*NN], g_xy[NB*NN], g_xz[NB*NN], g_xw[NB*NN];
__device__ float g_yx[NB*NN], g_yy[NB*NN], g_yz[NB*NN], g_yw[NB*NN];
__device__ float g_f[NB*NN], g_g[NB*NN];
__device__ float g_part[512];

__device__ __forceinline__ float ex2f_(float x) {
    float r; asm("ex2.approx.ftz.f32 %0, %1;" : "=f"(r) : "f"(x)); return r;
}
__device__ __forceinline__ float lg2f_(float x) {
    float r; asm("lg2.approx.ftz.f32 %0, %1;" : "=f"(r) : "f"(x)); return r;
}
// packed f32x2 helpers (sm_103a)
__device__ __forceinline__ ull ffma2u(ull a, ull b, ull c) {
    ull d; asm("fma.rn.f32x2 %0, %1, %2, %3;" : "=l"(d) : "l"(a), "l"(b), "l"(c)); return d;
}
__device__ __forceinline__ ull fadd2u(ull a, ull b) {
    ull d; asm("add.rn.f32x2 %0, %1, %2;" : "=l"(d) : "l"(a), "l"(b)); return d;
}
__device__ __forceinline__ ull f2u(float lo, float hi) {
    ull r; asm("mov.b64 %0, {%1, %2};" : "=l"(r) : "f"(lo), "f"(hi)); return r;
}
__device__ __forceinline__ float2 u2f(ull v) {
    float2 f; asm("mov.b64 {%0, %1}, %2;" : "=f"(f.x), "=f"(f.y) : "l"(v)); return f;
}

// Pack coordinates + squared norms into SoA arrays, zero duals.
__global__ void prep_kernel(const float* __restrict__ x, const float* __restrict__ y) {
    int i = blockIdx.x * blockDim.x + threadIdx.x;
    if (i >= NB * NN) return;
    float x0 = x[3*i], x1 = x[3*i+1], x2 = x[3*i+2];
    g_xx[i] = x0; g_xy[i] = x1; g_xz[i] = x2;
    g_xw[i] = x0*x0 + x1*x1 + x2*x2;
    float y0 = y[3*i], y1 = y[3*i+1], y2 = y[3*i+2];
    g_yx[i] = y0; g_yy[i] = y1; g_yz[i] = y2;
    g_yw[i] = y0*y0 + y1*y1 + y2*y2;
    g_f[i] = 0.f; g_g[i] = 0.f;
}

// One chunk of 8 columns: packed f32x2 dot, chunk-max rescale, f32 ex2, sum.
__device__ __forceinline__ void chunk8(const float* __restrict__ syx,
                                       const float* __restrict__ syy,
                                       const float* __restrict__ syz,
                                       const float* __restrict__ sgh,
                                       int m, ull axp, ull ayp, ull azp,
                                       float& mx, float& s) {
    ulonglong2 X0 = *(const ulonglong2*)(syx + m);
    ulonglong2 X1 = *(const ulonglong2*)(syx + m + 4);
    ulonglong2 Y0 = *(const ulonglong2*)(syy + m);
    ulonglong2 Y1 = *(const ulonglong2*)(syy + m + 4);
    ulonglong2 Z0 = *(const ulonglong2*)(syz + m);
    ulonglong2 Z1 = *(const ulonglong2*)(syz + m + 4);
    ulonglong2 G0 = *(const ulonglong2*)(sgh + m);
    ulonglong2 G1 = *(const ulonglong2*)(sgh + m + 4);

    ull p0 = ffma2u(axp, X0.x, ffma2u(ayp, Y0.x, ffma2u(azp, Z0.x, G0.x)));
    ull p1 = ffma2u(axp, X0.y, ffma2u(ayp, Y0.y, ffma2u(azp, Z0.y, G0.y)));
    ull p2 = ffma2u(axp, X1.x, ffma2u(ayp, Y1.x, ffma2u(azp, Z1.x, G1.x)));
    ull p3 = ffma2u(axp, X1.y, ffma2u(ayp, Y1.y, ffma2u(azp, Z1.y, G1.y)));

    float2 f0 = u2f(p0), f1 = u2f(p1), f2v = u2f(p2), f3 = u2f(p3);
    float cm = fmaxf(fmaxf(fmaxf(f0.x, f0.y), fmaxf(f1.x, f1.y)),
                     fmaxf(fmaxf(f2v.x, f2v.y), fmaxf(f3.x, f3.y)));
    float nm = fmaxf(mx, cm);
    float r  = ex2f_(mx - nm);       // ex2(0)=1 exactly when max unchanged
    mx = nm;

    ull nmp = f2u(-nm, -nm);
    float2 q0 = u2f(fadd2u(p0, nmp));
    float2 q1 = u2f(fadd2u(p1, nmp));
    float2 q2 = u2f(fadd2u(p2, nmp));
    float2 q3 = u2f(fadd2u(p3, nmp));

    float e0 = ex2f_(q0.x), e1 = ex2f_(q0.y);
    float e2 = ex2f_(q1.x), e3 = ex2f_(q1.y);
    float e4 = ex2f_(q2.x), e5 = ex2f_(q2.y);
    float e6 = ex2f_(q3.x), e7 = ex2f_(q3.y);
    float sum = ((e0 + e1) + (e2 + e3)) + ((e4 + e5) + (e6 + e7));
    s = fmaf(s, r, sum);
}

// One Sinkhorn half-step. dir==0: f from g (rows = x pts), dir==1: g from f.
// CTA = 512 thr = 16 warps, covers 64 rows x 2048 cols of one batch.
// warp w: row-half h = w>>3 (rows rowbase + h*32 + lane), strip = w&7
// (cols [strip*256, strip*256+256)), 2 independent accumulator streams.
// grid = 256 CTAs at 2 CTAs/SM -> ALL resident, single wave, no tail.
__global__ __launch_bounds__(512, 2) void upd_kernel(int dir) {
    const float *rx, *ry, *rz, *rw, *cx, *cy, *cz, *cw, *din;
    float* dout;
    if (dir == 0) {
        rx = g_xx; ry = g_xy; rz = g_xz; rw = g_xw;
        cx = g_yx; cy = g_yy; cz = g_yz; cw = g_yw;
        din = g_g; dout = g_f;
    } else {
        rx = g_yx; ry = g_yy; rz = g_yz; rw = g_yw;
        cx = g_xx; cy = g_xy; cz = g_xz; cw = g_xw;
        din = g_f; dout = g_g;
    }

    __shared__ __align__(16) float syx[NN], syy[NN], syz[NN], sgh[NN];
    __shared__ float pm[16][32], ps[16][32];

    int tid     = threadIdx.x;
    int c       = blockIdx.x;
    int b       = c >> 5;                 // 32 CTAs per batch
    int base    = b * NN;
    int rowbase = (c & 31) << 6;          // 64 rows per CTA

    // fill SoA smem, gh = K*(din - |y|^2); 512 thr * 4 = 2048 -> one pass
    {
        int i = tid * 4;
        float4 vx = *(const float4*)(cx + base + i);
        float4 vy = *(const float4*)(cy + base + i);
        float4 vz = *(const float4*)(cz + base + i);
        float4 vw = *(const float4*)(cw + base + i);
        float4 vd = *(const float4*)(din + base + i);
        *(float4*)(syx + i) = vx;
        *(float4*)(syy + i) = vy;
        *(float4*)(syz + i) = vz;
        float4 g;
        g.x = KC * (vd.x - vw.x); g.y = KC * (vd.y - vw.y);
        g.z = KC * (vd.z - vw.z); g.w = KC * (vd.w - vw.w);
        *(float4*)(sgh + i) = g;
    }
    __syncthreads();

    int w     = tid >> 5;
    int lane  = tid & 31;
    int h     = w >> 3;                   // row half
    int strip = w & 7;                    // 256-col strip
    int n     = rowbase + (h << 5) + lane;

    float xb = rx[base + n], yb = ry[base + n], zb = rz[base + n], wb = rw[base + n];
    float ax = 2.f * KC * xb, ay = 2.f * KC * yb, az = 2.f * KC * zb;
    ull axp = f2u(ax, ax), ayp = f2u(ay, ay), azp = f2u(az, az);

    float mx0 = -1e30f, s0 = 0.f;
    float mx1 = -1e30f, s1 = 0.f;
    int m0 = strip << 8;                  // 256-col strip

#pragma unroll 1
    for (int m = m0; m < m0 + 256; m += 16) {
        chunk8(syx, syy, syz, sgh, m,     axp, ayp, azp, mx0, s0);
        chunk8(syx, syy, syz, sgh, m + 8, axp, ayp, azp, mx1, s1);
    }

    // merge the two streams
    float M = fmaxf(mx0, mx1);
    float S = fmaf(s0, ex2f_(mx0 - M), s1 * ex2f_(mx1 - M));

    pm[w][lane] = M;
    ps[w][lane] = S;
    __syncthreads();

    // warps 0 and 8 merge the 8 strips of their row half
    if (strip == 0) {
        int j0 = h << 3;
        float Mm = pm[j0][lane];
#pragma unroll
        for (int j = 1; j < 8; j++) Mm = fmaxf(Mm, pm[j0 + j][lane]);
        float Sm = 0.f;
#pragma unroll
        for (int j = 0; j < 8; j++) Sm += ps[j0 + j][lane] * ex2f_(pm[j0 + j][lane] - Mm);
        // reapply the per-row shift -K*|x_n|^2 dropped from the loop
        float lse2 = (Mm - KC * wb) + lg2f_(Sm);
        dout[base + n] = C1F - C2F * lse2;   // eps*log_mu - eps*ln2*lse2
    }
}

// dis sum: total = sum_{b,n,m} exp((f+g-C)/eps) * C;  result = total / B
__global__ __launch_bounds__(256) void fin_kernel() {
    __shared__ __align__(16) float syx[NN], syy[NN], syz[NN], syw[NN], sg[NN];
    __shared__ float wsum[8];

    int tid  = threadIdx.x;
    int b    = blockIdx.x >> 6;
    int base = b * NN;

    for (int i = tid * 4; i < NN; i += 1024) {
        *(float4*)(syx + i) = *(const float4*)(g_yx + base + i);
        *(float4*)(syy + i) = *(const float4*)(g_yy + base + i);
        *(float4*)(syz + i) = *(const float4*)(g_yz + base + i);
        *(float4*)(syw + i) = *(const float4*)(g_yw + base + i);
        *(float4*)(sg  + i) = *(const float4*)(g_g  + base + i);
    }
    __syncthreads();

    int w    = tid >> 5;
    int lane = tid & 31;
    int n    = ((blockIdx.x & 63) << 5) + lane;

    float xb = g_xx[base + n], yb = g_xy[base + n], zb = g_xz[base + n], wb = g_xw[base + n];
    float Kf = KC * g_f[base + n];
    float acc = 0.f;

    int m0 = w << 8;
    for (int m = m0; m < m0 + 256; ++m) {
        float d = fmaf(xb, syx[m], fmaf(yb, syy[m], zb * syz[m]));
        float c = fmaf(-2.f, d, wb + syw[m]);
        c = fmaxf(c, 0.f);
        float arg = fmaf(KC, sg[m] - c, Kf);   // K*(f + g - c)
        acc = fmaf(ex2f_(arg), c, acc);        // underflow -> 0 harmlessly
    }

    for (int o = 16; o; o >>= 1) acc += __shfl_xor_sync(0xffffffffu, acc, o);
    if (lane == 0) wsum[w] = acc;
    __syncthreads();
    if (tid == 0) {
        float t = 0.f;
#pragma unroll
        for (int j = 0; j < 8; j++) t += wsum[j];
        g_part[blockIdx.x] = t;
    }
}

// Deterministic final reduction of 512 block partials.
__global__ void red_kernel(float* __restrict__ out) {
    __shared__ float sm[512];
    int t = threadIdx.x;
    sm[t] = g_part[t];
    __syncthreads();
    for (int o = 256; o; o >>= 1) {
        if (t < o) sm[t] += sm[t + o];
        __syncthreads();
    }
    if (t == 0) out[0] = sm[0] * 0.125f;   // / B
}

extern "C" void kernel_launch(void* const* d_in, const int* in_sizes, int n_in,
                              void* d_out, int out_size) {
    const float* x = (const float*)d_in[0];
    const float* y = (const float*)d_in[1];

    prep_kernel<<<(NB * NN + 255) / 256, 256>>>(x, y);

    for (int it = 0; it < NITERS; ++it) {
        upd_kernel<<<256, 512>>>(0);   // f from g
        upd_kernel<<<256, 512>>>(1);   // g from new f
    }

    fin_kernel<<<512, 256>>>();
    red_kernel<<<1, 512>>>((float*)d_out);
}

// round 17
// speedup vs baseline: 1.0061x; 1.0032x over previous
#include <cuda_runtime.h>

typedef unsigned long long ull;

#define NB 8
#define NN 2048
#define NITERS 50

// K = log2(e)/eps, eps = 0.005
#define KC 288.53900817779268f
// C1 = eps*log_mu = -0.005*ln(2048)
#define C1F (-0.038123094930796994f)
// C2 = eps*ln(2)
#define C2F 0.0034657359027997265f

// SoA coordinate/norm arrays (x-side and y-side), duals, partials.
__device__ float g_xx[NB*NN], g_xy[NB*NN], g_xz[NB*NN], g_xw[NB*NN];
__device__ float g_yx[NB*NN], g_yy[NB*NN], g_yz[NB*NN], g_yw[NB*NN];
__device__ float g_f[NB*NN], g_g[NB*NN];
__device__ float g_part[512];

__device__ __forceinline__ float ex2f_(float x) {
    float r; asm("ex2.approx.ftz.f32 %0, %1;" : "=f"(r) : "f"(x)); return r;
}
__device__ __forceinline__ float lg2f_(float x) {
    float r; asm("lg2.approx.ftz.f32 %0, %1;" : "=f"(r) : "f"(x)); return r;
}
// packed f32x2 helpers (sm_103a)
__device__ __forceinline__ ull ffma2u(ull a, ull b, ull c) {
    ull d; asm("fma.rn.f32x2 %0, %1, %2, %3;" : "=l"(d) : "l"(a), "l"(b), "l"(c)); return d;
}
__device__ __forceinline__ ull fadd2u(ull a, ull b) {
    ull d; asm("add.rn.f32x2 %0, %1, %2;" : "=l"(d) : "l"(a), "l"(b)); return d;
}
__device__ __forceinline__ ull f2u(float lo, float hi) {
    ull r; asm("mov.b64 %0, {%1, %2};" : "=l"(r) : "f"(lo), "f"(hi)); return r;
}
__device__ __forceinline__ float2 u2f(ull v) {
    float2 f; asm("mov.b64 {%0, %1}, %2;" : "=f"(f.x), "=f"(f.y) : "l"(v)); return f;
}

// Pack coordinates + squared norms into SoA arrays, zero duals.
__global__ void prep_kernel(const float* __restrict__ x, const float* __restrict__ y) {
    int i = blockIdx.x * blockDim.x + threadIdx.x;
    if (i >= NB * NN) return;
    float x0 = x[3*i], x1 = x[3*i+1], x2 = x[3*i+2];
    g_xx[i] = x0; g_xy[i] = x1; g_xz[i] = x2;
    g_xw[i] = x0*x0 + x1*x1 + x2*x2;
    float y0 = y[3*i], y1 = y[3*i+1], y2 = y[3*i+2];
    g_yx[i] = y0; g_yy[i] = y1; g_yz[i] = y2;
    g_yw[i] = y0*y0 + y1*y1 + y2*y2;
    g_f[i] = 0.f; g_g[i] = 0.f;
}

// One chunk of 8 columns: packed f32x2 dot, chunk-max rescale, f32 ex2, sum.
__device__ __forceinline__ void chunk8(const float* __restrict__ syx,
                                       const float* __restrict__ syy,
                                       const float* __restrict__ syz,
                                       const float* __restrict__ sgh,
                                       int m, ull axp, ull ayp, ull azp,
                                       float& mx, float& s) {
    ulonglong2 X0 = *(const ulonglong2*)(syx + m);
    ulonglong2 X1 = *(const ulonglong2*)(syx + m + 4);
    ulonglong2 Y0 = *(const ulonglong2*)(syy + m);
    ulonglong2 Y1 = *(const ulonglong2*)(syy + m + 4);
    ulonglong2 Z0 = *(const ulonglong2*)(syz + m);
    ulonglong2 Z1 = *(const ulonglong2*)(syz + m + 4);
    ulonglong2 G0 = *(const ulonglong2*)(sgh + m);
    ulonglong2 G1 = *(const ulonglong2*)(sgh + m + 4);

    ull p0 = ffma2u(axp, X0.x, ffma2u(ayp, Y0.x, ffma2u(azp, Z0.x, G0.x)));
    ull p1 = ffma2u(axp, X0.y, ffma2u(ayp, Y0.y, ffma2u(azp, Z0.y, G0.y)));
    ull p2 = ffma2u(axp, X1.x, ffma2u(ayp, Y1.x, ffma2u(azp, Z1.x, G1.x)));
    ull p3 = ffma2u(axp, X1.y, ffma2u(ayp, Y1.y, ffma2u(azp, Z1.y, G1.y)));

    float2 f0 = u2f(p0), f1 = u2f(p1), f2v = u2f(p2), f3 = u2f(p3);
    float cm = fmaxf(fmaxf(fmaxf(f0.x, f0.y), fmaxf(f1.x, f1.y)),
                     fmaxf(fmaxf(f2v.x, f2v.y), fmaxf(f3.x, f3.y)));
    float nm = fmaxf(mx, cm);
    float r  = ex2f_(mx - nm);       // ex2(0)=1 exactly when max unchanged
    mx = nm;

    ull nmp = f2u(-nm, -nm);
    float2 q0 = u2f(fadd2u(p0, nmp));
    float2 q1 = u2f(fadd2u(p1, nmp));
    float2 q2 = u2f(fadd2u(p2, nmp));
    float2 q3 = u2f(fadd2u(p3, nmp));

    float e0 = ex2f_(q0.x), e1 = ex2f_(q0.y);
    float e2 = ex2f_(q1.x), e3 = ex2f_(q1.y);
    float e4 = ex2f_(q2.x), e5 = ex2f_(q2.y);
    float e6 = ex2f_(q3.x), e7 = ex2f_(q3.y);
    float sum = ((e0 + e1) + (e2 + e3)) + ((e4 + e5) + (e6 + e7));
    s = fmaf(s, r, sum);
}

// One Sinkhorn half-step. dir==0: f from g (rows = x pts), dir==1: g from f.
// CTA = 512 thr = 16 warps, covers 64 rows x 2048 cols of one batch.
// warp w: row-half h = w>>3 (rows rowbase + h*32 + lane), strip = w&7
// (cols [strip*256, strip*256+256)), 2 independent accumulator streams.
// grid = 256 CTAs at 2 CTAs/SM -> ALL resident, single wave, no tail.
__global__ __launch_bounds__(512, 2) void upd_kernel(int dir) {
    const float *rx, *ry, *rz, *rw, *cx, *cy, *cz, *cw, *din;
    float* dout;
    if (dir == 0) {
        rx = g_xx; ry = g_xy; rz = g_xz; rw = g_xw;
        cx = g_yx; cy = g_yy; cz = g_yz; cw = g_yw;
        din = g_g; dout = g_f;
    } else {
        rx = g_yx; ry = g_yy; rz = g_yz; rw = g_yw;
        cx = g_xx; cy = g_xy; cz = g_xz; cw = g_xw;
        din = g_f; dout = g_g;
    }

    __shared__ __align__(16) float syx[NN], syy[NN], syz[NN], sgh[NN];
    __shared__ float pm[16][32], ps[16][32];

    int tid     = threadIdx.x;
    int c       = blockIdx.x;
    int b       = c >> 5;                 // 32 CTAs per batch
    int base    = b * NN;
    int rowbase = (c & 31) << 6;          // 64 rows per CTA

    // fill SoA smem, gh = K*(din - |y|^2); 512 thr * 4 = 2048 -> one pass
    {
        int i = tid * 4;
        float4 vx = *(const float4*)(cx + base + i);
        float4 vy = *(const float4*)(cy + base + i);
        float4 vz = *(const float4*)(cz + base + i);
        float4 vw = *(const float4*)(cw + base + i);
        float4 vd = *(const float4*)(din + base + i);
        *(float4*)(syx + i) = vx;
        *(float4*)(syy + i) = vy;
        *(float4*)(syz + i) = vz;
        float4 g;
        g.x = KC * (vd.x - vw.x); g.y = KC * (vd.y - vw.y);
        g.z = KC * (vd.z - vw.z); g.w = KC * (vd.w - vw.w);
        *(float4*)(sgh + i) = g;
    }
    __syncthreads();

    int w     = tid >> 5;
    int lane  = tid & 31;
    int h     = w >> 3;                   // row half
    int strip = w & 7;                    // 256-col strip
    int n     = rowbase + (h << 5) + lane;

    float xb = rx[base + n], yb = ry[base + n], zb = rz[base + n], wb = rw[base + n];
    float ax = 2.f * KC * xb, ay = 2.f * KC * yb, az = 2.f * KC * zb;
    ull axp = f2u(ax, ax), ayp = f2u(ay, ay), azp = f2u(az, az);

    float mx0 = -1e30f, s0 = 0.f;
    float mx1 = -1e30f, s1 = 0.f;
    int m0 = strip << 8;                  // 256-col strip

#pragma unroll 1
    for (int m = m0; m < m0 + 256; m += 16) {
        chunk8(syx, syy, syz, sgh, m,     axp, ayp, azp, mx0, s0);
        chunk8(syx, syy, syz, sgh, m + 8, axp, ayp, azp, mx1, s1);
    }

    // merge the two streams
    float M = fmaxf(mx0, mx1);
    float S = fmaf(s0, ex2f_(mx0 - M), s1 * ex2f_(mx1 - M));

    pm[w][lane] = M;
    ps[w][lane] = S;
    __syncthreads();

    // warps 0 and 8 merge the 8 strips of their row half
    if (strip == 0) {
        int j0 = h << 3;
        float Mm = pm[j0][lane];
#pragma unroll
        for (int j = 1; j < 8; j++) Mm = fmaxf(Mm, pm[j0 + j][lane]);
        float Sm = 0.f;
#pragma unroll
        for (int j = 0; j < 8; j++) Sm += ps[j0 + j][lane] * ex2f_(pm[j0 + j][lane] - Mm);
        // reapply the per-row shift -K*|x_n|^2 dropped from the loop
        float lse2 = (Mm - KC * wb) + lg2f_(Sm);
        dout[base + n] = C1F - C2F * lse2;   // eps*log_mu - eps*ln2*lse2
    }
}

// dis sum: total = sum_{b,n,m} exp((f+g-C)/eps) * C;  result = total / B
__global__ __launch_bounds__(256) void fin_kernel() {
    __shared__ __align__(16) float syx[NN], syy[NN], syz[NN], syw[NN], sg[NN];
    __shared__ float wsum[8];

    int tid  = threadIdx.x;
    int b    = blockIdx.x >> 6;
    int base = b * NN;

    for (int i = tid * 4; i < NN; i += 1024) {
        *(float4*)(syx + i) = *(const float4*)(g_yx + base + i);
        *(float4*)(syy + i) = *(const float4*)(g_yy + base + i);
        *(float4*)(syz + i) = *(const float4*)(g_yz + base + i);
        *(float4*)(syw + i) = *(const float4*)(g_yw + base + i);
        *(float4*)(sg  + i) = *(const float4*)(g_g  + base + i);
    }
    __syncthreads();

    int w    = tid >> 5;
    int lane = tid & 31;
    int n    = ((blockIdx.x & 63) << 5) + lane;

    float xb = g_xx[base + n], yb = g_xy[base + n], zb = g_xz[base + n], wb = g_xw[base + n];
    float Kf = KC * g_f[base + n];
    float acc = 0.f;

    int m0 = w << 8;
    for (int m = m0; m < m0 + 256; ++m) {
        float d = fmaf(xb, syx[m], fmaf(yb, syy[m], zb * syz[m]));
        float c = fmaf(-2.f, d, wb + syw[m]);
        c = fmaxf(c, 0.f);
        float arg = fmaf(KC, sg[m] - c, Kf);   // K*(f + g - c)
        acc = fmaf(ex2f_(arg), c, acc);        // underflow -> 0 harmlessly
    }

    for (int o = 16; o; o >>= 1) acc += __shfl_xor_sync(0xffffffffu, acc, o);
    if (lane == 0) wsum[w] = acc;
    __syncthreads();
    if (tid == 0) {
        float t = 0.f;
#pragma unroll
        for (int j = 0; j < 8; j++) t += wsum[j];
        g_part[blockIdx.x] = t;
    }
}

// Deterministic final reduction of 512 block partials.
__global__ void red_kernel(float* __restrict__ out) {
    __shared__ float sm[512];
    int t = threadIdx.x;
    sm[t] = g_part[t];
    __syncthreads();
    for (int o = 256; o; o >>= 1) {
        if (t < o) sm[t] += sm[t + o];
        __syncthreads();
    }
    if (t == 0) out[0] = sm[0] * 0.125f;   // / B
}

extern "C" void kernel_launch(void* const* d_in, const int* in_sizes, int n_in,
                              void* d_out, int out_size) {
    const float* x = (const float*)d_in[0];
    const float* y = (const float*)d_in[1];

    prep_kernel<<<(NB * NN + 255) / 256, 256>>>(x, y);

    for (int it = 0; it < NITERS; ++it) {
        upd_kernel<<<256, 512>>>(0);   // f from g
        upd_kernel<<<256, 512>>>(1);   // g from new f
    }

    fin_kernel<<<512, 256>>>();
    red_kernel<<<1, 512>>>((float*)d_out);
}